// round 14
// baseline (speedup 1.0000x reference)
#include <cuda_runtime.h>
#include <cuda_bf16.h>

// Problem dims (fixed by the reference)
#define BB 4
#define NN_SEQ 4096
#define DD 1024
#define M_TOTAL (BB * NN_SEQ)   // 16384

// -----------------------------------------------------------------------------
// Scratch: __device__ globals (no cudaMalloc allowed anywhere).
// q,k,v,y: 64 MiB each; ctx: 16 MiB. Total ~272 MiB.
// -----------------------------------------------------------------------------
__device__ float g_q[(size_t)M_TOTAL * DD];
__device__ float g_k[(size_t)M_TOTAL * DD];
__device__ float g_v[(size_t)M_TOTAL * DD];
__device__ float g_ctx[(size_t)BB * DD * DD];
__device__ float g_y[(size_t)M_TOTAL * DD];

// -----------------------------------------------------------------------------
// Tiled fp32 GEMM: C = alpha * op(A) * B (+ bias)
//   TRANS_A=false: A is [M,K] row-major (lda=K)
//   TRANS_A=true : A is [K,M] row-major (lda=M)  (i.e. compute A^T * B)
//   B is [K,N] row-major (ldb=N). C is [M,N] row-major.
// Tile: BM=BN=128, BK=8; 256 threads; 8x8 accumulators per thread.
// All dims in this problem are multiples of 128 (M) / 128 (N) / 8 (K):
// no bounds checks needed.
// -----------------------------------------------------------------------------
template <bool TRANS_A, bool ADD_BIAS>
__global__ __launch_bounds__(256)
void sgemm_kernel(const float* __restrict__ A,
                  const float* __restrict__ Bm,
                  float* __restrict__ C,
                  const float* __restrict__ bias,
                  int M, int Nn, int K, float alpha,
                  size_t strideA, size_t strideB, size_t strideC)
{
    constexpr int BM = 128, BN = 128, BK = 8;

    A  += (size_t)blockIdx.z * strideA;
    Bm += (size_t)blockIdx.z * strideB;
    C  += (size_t)blockIdx.z * strideC;

    __shared__ float As[BK][BM];
    __shared__ float Bs[BK][BN];

    const int tid = threadIdx.x;
    const int m0 = blockIdx.y * BM;
    const int n0 = blockIdx.x * BN;

    const int ty = tid >> 4;          // 0..15  (m direction)
    const int tx = tid & 15;          // 0..15  (n direction)

    float acc[8][8];
    #pragma unroll
    for (int i = 0; i < 8; i++)
        #pragma unroll
        for (int j = 0; j < 8; j++)
            acc[i][j] = 0.f;

    for (int k0 = 0; k0 < K; k0 += BK) {
        // ---- load A tile ----
        if (TRANS_A) {
            // A[k][m], tile 8 x 128, vectorized along m
            const int r = tid >> 5;          // 0..7   (k)
            const int c = (tid & 31) * 4;    // 0..124 (m)
            float4 va = *reinterpret_cast<const float4*>(
                &A[(size_t)(k0 + r) * M + (m0 + c)]);
            *reinterpret_cast<float4*>(&As[r][c]) = va;
        } else {
            // A[m][k], tile 128 x 8, vectorized along k, store transposed
            const int r = tid >> 1;          // 0..127 (m)
            const int c = (tid & 1) * 4;     // 0 or 4 (k)
            float4 va = *reinterpret_cast<const float4*>(
                &A[(size_t)(m0 + r) * K + (k0 + c)]);
            As[c + 0][r] = va.x;
            As[c + 1][r] = va.y;
            As[c + 2][r] = va.z;
            As[c + 3][r] = va.w;
        }
        // ---- load B tile (always [K,N]) ----
        {
            const int r = tid >> 5;          // 0..7   (k)
            const int c = (tid & 31) * 4;    // 0..124 (n)
            float4 vb = *reinterpret_cast<const float4*>(
                &Bm[(size_t)(k0 + r) * Nn + (n0 + c)]);
            *reinterpret_cast<float4*>(&Bs[r][c]) = vb;
        }
        __syncthreads();

        #pragma unroll
        for (int kk = 0; kk < BK; kk++) {
            float ar[8], br[8];
            float4 a0 = *reinterpret_cast<const float4*>(&As[kk][ty * 8]);
            float4 a1 = *reinterpret_cast<const float4*>(&As[kk][ty * 8 + 4]);
            float4 b0 = *reinterpret_cast<const float4*>(&Bs[kk][tx * 8]);
            float4 b1 = *reinterpret_cast<const float4*>(&Bs[kk][tx * 8 + 4]);
            ar[0]=a0.x; ar[1]=a0.y; ar[2]=a0.z; ar[3]=a0.w;
            ar[4]=a1.x; ar[5]=a1.y; ar[6]=a1.z; ar[7]=a1.w;
            br[0]=b0.x; br[1]=b0.y; br[2]=b0.z; br[3]=b0.w;
            br[4]=b1.x; br[5]=b1.y; br[6]=b1.z; br[7]=b1.w;
            #pragma unroll
            for (int i = 0; i < 8; i++)
                #pragma unroll
                for (int j = 0; j < 8; j++)
                    acc[i][j] = fmaf(ar[i], br[j], acc[i][j]);
        }
        __syncthreads();
    }

    // ---- epilogue ----
    #pragma unroll
    for (int i = 0; i < 8; i++) {
        float* crow = C + (size_t)(m0 + ty * 8 + i) * Nn + (n0 + tx * 8);
        #pragma unroll
        for (int j = 0; j < 8; j += 4) {
            float4 o;
            o.x = acc[i][j + 0] * alpha;
            o.y = acc[i][j + 1] * alpha;
            o.z = acc[i][j + 2] * alpha;
            o.w = acc[i][j + 3] * alpha;
            if (ADD_BIAS) {
                const float* bp = bias + (n0 + tx * 8 + j);
                o.x += bp[0]; o.y += bp[1]; o.z += bp[2]; o.w += bp[3];
            }
            *reinterpret_cast<float4*>(crow + j) = o;
        }
    }
}

// -----------------------------------------------------------------------------
// Row softmax over last dim (1024) — one block per row, 256 threads x float4.
// -----------------------------------------------------------------------------
__global__ __launch_bounds__(256)
void softmax_rows_kernel(float* __restrict__ data)
{
    __shared__ float sh[8];
    const int lane = threadIdx.x & 31;
    const int wid  = threadIdx.x >> 5;

    float4* p = reinterpret_cast<float4*>(data + (size_t)blockIdx.x * DD);
    float4 v = p[threadIdx.x];

    // ---- block max ----
    float m = fmaxf(fmaxf(v.x, v.y), fmaxf(v.z, v.w));
    #pragma unroll
    for (int o = 16; o; o >>= 1) m = fmaxf(m, __shfl_xor_sync(0xffffffffu, m, o));
    if (lane == 0) sh[wid] = m;
    __syncthreads();
    {
        float t = sh[threadIdx.x & 7];
        #pragma unroll
        for (int o = 4; o; o >>= 1) t = fmaxf(t, __shfl_xor_sync(0xffffffffu, t, o));
        m = t;  // every thread now has (warp-local copy of) the row max
    }
    __syncthreads();

    // ---- block sum of exp ----
    float e0 = __expf(v.x - m), e1 = __expf(v.y - m);
    float e2 = __expf(v.z - m), e3 = __expf(v.w - m);
    float s = (e0 + e1) + (e2 + e3);
    #pragma unroll
    for (int o = 16; o; o >>= 1) s += __shfl_xor_sync(0xffffffffu, s, o);
    if (lane == 0) sh[wid] = s;
    __syncthreads();
    {
        float t = sh[threadIdx.x & 7];
        #pragma unroll
        for (int o = 4; o; o >>= 1) t += __shfl_xor_sync(0xffffffffu, t, o);
        s = t;
    }

    const float inv = __frcp_rn(s);
    float4 o4;
    o4.x = e0 * inv; o4.y = e1 * inv; o4.z = e2 * inv; o4.w = e3 * inv;
    p[threadIdx.x] = o4;
}

// -----------------------------------------------------------------------------
// Column softmax over sequence dim (axis=-2): for each (b, d), softmax over n.
// Block = 256 threads = 32 columns (d) x 8 n-slices. Online softmax per slice,
// merge partials in shared memory, then a normalize pass.
// -----------------------------------------------------------------------------
__global__ __launch_bounds__(256)
void softmax_cols_kernel(float* __restrict__ data)
{
    const int tx = threadIdx.x & 31;   // column within block
    const int ty = threadIdx.x >> 5;   // n-slice 0..7
    const int b  = blockIdx.y;
    const int d  = blockIdx.x * 32 + tx;

    float* base = data + (size_t)b * NN_SEQ * DD + d;
    const int chunk = NN_SEQ / 8;      // 512
    const int n0 = ty * chunk;

    float m = -1e30f, s = 0.f;
    #pragma unroll 8
    for (int n = n0; n < n0 + chunk; n++) {
        float v = __ldg(&base[(size_t)n * DD]);
        float nm = fmaxf(m, v);
        s = s * __expf(m - nm) + __expf(v - nm);
        m = nm;
    }

    __shared__ float shm[8][32];
    __shared__ float shs[8][32];
    shm[ty][tx] = m;
    shs[ty][tx] = s;
    __syncthreads();

    float M = -1e30f;
    #pragma unroll
    for (int i = 0; i < 8; i++) M = fmaxf(M, shm[i][tx]);
    float S = 0.f;
    #pragma unroll
    for (int i = 0; i < 8; i++) S += shs[i][tx] * __expf(shm[i][tx] - M);
    const float inv = __frcp_rn(S);

    #pragma unroll 8
    for (int n = n0; n < n0 + chunk; n++) {
        float v = base[(size_t)n * DD];
        base[(size_t)n * DD] = __expf(v - M) * inv;
    }
}

// -----------------------------------------------------------------------------
// kernel_launch: 8 graph-capturable launches on the default stream.
//   Inputs (metadata order): x, Wq, Wk, Wv, Wo, bo
//   Output: [B, N, D_OUT] fp32
// -----------------------------------------------------------------------------
extern "C" void kernel_launch(void* const* d_in, const int* /*in_sizes*/, int /*n_in*/,
                              void* d_out, int /*out_size*/)
{
    const float* x  = (const float*)d_in[0];
    const float* Wq = (const float*)d_in[1];
    const float* Wk = (const float*)d_in[2];
    const float* Wv = (const float*)d_in[3];
    const float* Wo = (const float*)d_in[4];
    const float* bo = (const float*)d_in[5];
    float* out = (float*)d_out;

    float *q, *k, *v, *ctx, *y;
    cudaGetSymbolAddress((void**)&q,   g_q);
    cudaGetSymbolAddress((void**)&k,   g_k);
    cudaGetSymbolAddress((void**)&v,   g_v);
    cudaGetSymbolAddress((void**)&ctx, g_ctx);
    cudaGetSymbolAddress((void**)&y,   g_y);

    const dim3 blk(256);
    const dim3 g_proj(DD / 128, M_TOTAL / 128, 1);            // (8, 128)
    const dim3 g_ctx(DD / 128, DD / 128, BB);                 // (8, 8, 4)
    const dim3 g_y(DD / 128, NN_SEQ / 128, BB);               // (8, 32, 4)

    const float scale_ctx = 0.125f;          // 1/sqrt(D_HEAD=64)
    const float scale_y   = 1.0f / (float)DD;

    // 1) projections: q_lin, k_lin, v = x @ W
    sgemm_kernel<false, false><<<g_proj, blk>>>(x, Wq, q, nullptr,
        M_TOTAL, DD, DD, 1.0f, 0, 0, 0);
    sgemm_kernel<false, false><<<g_proj, blk>>>(x, Wk, k, nullptr,
        M_TOTAL, DD, DD, 1.0f, 0, 0, 0);
    sgemm_kernel<false, false><<<g_proj, blk>>>(x, Wv, v, nullptr,
        M_TOTAL, DD, DD, 1.0f, 0, 0, 0);

    // 2) softmaxes
    softmax_rows_kernel<<<M_TOTAL, 256>>>(q);                 // over features
    softmax_cols_kernel<<<dim3(DD / 32, BB), 256>>>(k);       // over sequence

    // 3) ctx = (k^T @ v) * scale, per batch:  [D,N]x[N,D] -> [D,D]
    sgemm_kernel<true, false><<<g_ctx, blk>>>(k, v, ctx, nullptr,
        DD, DD, NN_SEQ, scale_ctx,
        (size_t)NN_SEQ * DD, (size_t)NN_SEQ * DD, (size_t)DD * DD);

    // 4) y = (q @ ctx) / D_OUT, per batch:  [N,D]x[D,D] -> [N,D]
    sgemm_kernel<false, false><<<g_y, blk>>>(q, ctx, y, nullptr,
        NN_SEQ, DD, DD, scale_y,
        (size_t)NN_SEQ * DD, (size_t)DD * DD, (size_t)NN_SEQ * DD);

    // 5) out = y @ Wo + bo
    sgemm_kernel<false, true><<<g_proj, blk>>>(y, Wo, out, bo,
        M_TOTAL, DD, DD, 1.0f, 0, 0, 0);
}

// round 15
// speedup vs baseline: 1.0021x; 1.0021x over previous
#include <cuda_runtime.h>
#include <cuda_bf16.h>

// Problem dims (fixed by the reference)
#define BB 4
#define NN_SEQ 4096
#define DD 1024
#define M_TOTAL (BB * NN_SEQ)   // 16384

// -----------------------------------------------------------------------------
// Scratch: __device__ globals (no cudaMalloc allowed anywhere).
// q,k,v,y: 64 MiB each; ctx: 16 MiB. Total ~272 MiB.
// -----------------------------------------------------------------------------
__device__ float g_q[(size_t)M_TOTAL * DD];
__device__ float g_k[(size_t)M_TOTAL * DD];
__device__ float g_v[(size_t)M_TOTAL * DD];
__device__ float g_ctx[(size_t)BB * DD * DD];
__device__ float g_y[(size_t)M_TOTAL * DD];

// -----------------------------------------------------------------------------
// Tiled fp32 GEMM: C = alpha * op(A) * B (+ bias)
//   TRANS_A=false: A is [M,K] row-major (lda=K)
//   TRANS_A=true : A is [K,M] row-major (lda=M)  (i.e. compute A^T * B)
//   B is [K,N] row-major (ldb=N). C is [M,N] row-major.
// Tile: BM=BN=128, BK=8; 256 threads; 8x8 accumulators per thread.
// All dims in this problem are multiples of 128 (M) / 128 (N) / 8 (K):
// no bounds checks needed.
// -----------------------------------------------------------------------------
template <bool TRANS_A, bool ADD_BIAS>
__global__ __launch_bounds__(256)
void sgemm_kernel(const float* __restrict__ A,
                  const float* __restrict__ Bm,
                  float* __restrict__ C,
                  const float* __restrict__ bias,
                  int M, int Nn, int K, float alpha,
                  size_t strideA, size_t strideB, size_t strideC)
{
    constexpr int BM = 128, BN = 128, BK = 8;

    A  += (size_t)blockIdx.z * strideA;
    Bm += (size_t)blockIdx.z * strideB;
    C  += (size_t)blockIdx.z * strideC;

    __shared__ float As[BK][BM];
    __shared__ float Bs[BK][BN];

    const int tid = threadIdx.x;
    const int m0 = blockIdx.y * BM;
    const int n0 = blockIdx.x * BN;

    const int ty = tid >> 4;          // 0..15  (m direction)
    const int tx = tid & 15;          // 0..15  (n direction)

    float acc[8][8];
    #pragma unroll
    for (int i = 0; i < 8; i++)
        #pragma unroll
        for (int j = 0; j < 8; j++)
            acc[i][j] = 0.f;

    for (int k0 = 0; k0 < K; k0 += BK) {
        // ---- load A tile ----
        if (TRANS_A) {
            // A[k][m], tile 8 x 128, vectorized along m
            const int r = tid >> 5;          // 0..7   (k)
            const int c = (tid & 31) * 4;    // 0..124 (m)
            float4 va = *reinterpret_cast<const float4*>(
                &A[(size_t)(k0 + r) * M + (m0 + c)]);
            *reinterpret_cast<float4*>(&As[r][c]) = va;
        } else {
            // A[m][k], tile 128 x 8, vectorized along k, store transposed
            const int r = tid >> 1;          // 0..127 (m)
            const int c = (tid & 1) * 4;     // 0 or 4 (k)
            float4 va = *reinterpret_cast<const float4*>(
                &A[(size_t)(m0 + r) * K + (k0 + c)]);
            As[c + 0][r] = va.x;
            As[c + 1][r] = va.y;
            As[c + 2][r] = va.z;
            As[c + 3][r] = va.w;
        }
        // ---- load B tile (always [K,N]) ----
        {
            const int r = tid >> 5;          // 0..7   (k)
            const int c = (tid & 31) * 4;    // 0..124 (n)
            float4 vb = *reinterpret_cast<const float4*>(
                &Bm[(size_t)(k0 + r) * Nn + (n0 + c)]);
            *reinterpret_cast<float4*>(&Bs[r][c]) = vb;
        }
        __syncthreads();

        #pragma unroll
        for (int kk = 0; kk < BK; kk++) {
            float ar[8], br[8];
            float4 a0 = *reinterpret_cast<const float4*>(&As[kk][ty * 8]);
            float4 a1 = *reinterpret_cast<const float4*>(&As[kk][ty * 8 + 4]);
            float4 b0 = *reinterpret_cast<const float4*>(&Bs[kk][tx * 8]);
            float4 b1 = *reinterpret_cast<const float4*>(&Bs[kk][tx * 8 + 4]);
            ar[0]=a0.x; ar[1]=a0.y; ar[2]=a0.z; ar[3]=a0.w;
            ar[4]=a1.x; ar[5]=a1.y; ar[6]=a1.z; ar[7]=a1.w;
            br[0]=b0.x; br[1]=b0.y; br[2]=b0.z; br[3]=b0.w;
            br[4]=b1.x; br[5]=b1.y; br[6]=b1.z; br[7]=b1.w;
            #pragma unroll
            for (int i = 0; i < 8; i++)
                #pragma unroll
                for (int j = 0; j < 8; j++)
                    acc[i][j] = fmaf(ar[i], br[j], acc[i][j]);
        }
        __syncthreads();
    }

    // ---- epilogue ----
    #pragma unroll
    for (int i = 0; i < 8; i++) {
        float* crow = C + (size_t)(m0 + ty * 8 + i) * Nn + (n0 + tx * 8);
        #pragma unroll
        for (int j = 0; j < 8; j += 4) {
            float4 o;
            o.x = acc[i][j + 0] * alpha;
            o.y = acc[i][j + 1] * alpha;
            o.z = acc[i][j + 2] * alpha;
            o.w = acc[i][j + 3] * alpha;
            if (ADD_BIAS) {
                const float* bp = bias + (n0 + tx * 8 + j);
                o.x += bp[0]; o.y += bp[1]; o.z += bp[2]; o.w += bp[3];
            }
            *reinterpret_cast<float4*>(crow + j) = o;
        }
    }
}

// -----------------------------------------------------------------------------
// Row softmax over last dim (1024) — one block per row, 256 threads x float4.
// -----------------------------------------------------------------------------
__global__ __launch_bounds__(256)
void softmax_rows_kernel(float* __restrict__ data)
{
    __shared__ float sh[8];
    const int lane = threadIdx.x & 31;
    const int wid  = threadIdx.x >> 5;

    float4* p = reinterpret_cast<float4*>(data + (size_t)blockIdx.x * DD);
    float4 v = p[threadIdx.x];

    // ---- block max ----
    float m = fmaxf(fmaxf(v.x, v.y), fmaxf(v.z, v.w));
    #pragma unroll
    for (int o = 16; o; o >>= 1) m = fmaxf(m, __shfl_xor_sync(0xffffffffu, m, o));
    if (lane == 0) sh[wid] = m;
    __syncthreads();
    {
        float t = sh[threadIdx.x & 7];
        #pragma unroll
        for (int o = 4; o; o >>= 1) t = fmaxf(t, __shfl_xor_sync(0xffffffffu, t, o));
        m = t;  // every thread now has (warp-local copy of) the row max
    }
    __syncthreads();

    // ---- block sum of exp ----
    float e0 = __expf(v.x - m), e1 = __expf(v.y - m);
    float e2 = __expf(v.z - m), e3 = __expf(v.w - m);
    float s = (e0 + e1) + (e2 + e3);
    #pragma unroll
    for (int o = 16; o; o >>= 1) s += __shfl_xor_sync(0xffffffffu, s, o);
    if (lane == 0) sh[wid] = s;
    __syncthreads();
    {
        float t = sh[threadIdx.x & 7];
        #pragma unroll
        for (int o = 4; o; o >>= 1) t += __shfl_xor_sync(0xffffffffu, t, o);
        s = t;
    }

    const float inv = __frcp_rn(s);
    float4 o4;
    o4.x = e0 * inv; o4.y = e1 * inv; o4.z = e2 * inv; o4.w = e3 * inv;
    p[threadIdx.x] = o4;
}

// -----------------------------------------------------------------------------
// Column softmax over sequence dim (axis=-2): for each (b, d), softmax over n.
// Block = 256 threads = 32 columns (d) x 8 n-slices. Online softmax per slice,
// merge partials in shared memory, then a normalize pass.
// -----------------------------------------------------------------------------
__global__ __launch_bounds__(256)
void softmax_cols_kernel(float* __restrict__ data)
{
    const int tx = threadIdx.x & 31;   // column within block
    const int ty = threadIdx.x >> 5;   // n-slice 0..7
    const int b  = blockIdx.y;
    const int d  = blockIdx.x * 32 + tx;

    float* base = data + (size_t)b * NN_SEQ * DD + d;
    const int chunk = NN_SEQ / 8;      // 512
    const int n0 = ty * chunk;

    float m = -1e30f, s = 0.f;
    #pragma unroll 8
    for (int n = n0; n < n0 + chunk; n++) {
        float v = __ldg(&base[(size_t)n * DD]);
        float nm = fmaxf(m, v);
        s = s * __expf(m - nm) + __expf(v - nm);
        m = nm;
    }

    __shared__ float shm[8][32];
    __shared__ float shs[8][32];
    shm[ty][tx] = m;
    shs[ty][tx] = s;
    __syncthreads();

    float M = -1e30f;
    #pragma unroll
    for (int i = 0; i < 8; i++) M = fmaxf(M, shm[i][tx]);
    float S = 0.f;
    #pragma unroll
    for (int i = 0; i < 8; i++) S += shs[i][tx] * __expf(shm[i][tx] - M);
    const float inv = __frcp_rn(S);

    #pragma unroll 8
    for (int n = n0; n < n0 + chunk; n++) {
        float v = base[(size_t)n * DD];
        base[(size_t)n * DD] = __expf(v - M) * inv;
    }
}

// -----------------------------------------------------------------------------
// kernel_launch: 8 graph-capturable launches on the default stream.
//   Inputs (metadata order): x, Wq, Wk, Wv, Wo, bo
//   Output: [B, N, D_OUT] fp32
// -----------------------------------------------------------------------------
extern "C" void kernel_launch(void* const* d_in, const int* /*in_sizes*/, int /*n_in*/,
                              void* d_out, int /*out_size*/)
{
    const float* x  = (const float*)d_in[0];
    const float* Wq = (const float*)d_in[1];
    const float* Wk = (const float*)d_in[2];
    const float* Wv = (const float*)d_in[3];
    const float* Wo = (const float*)d_in[4];
    const float* bo = (const float*)d_in[5];
    float* out = (float*)d_out;

    float *q, *k, *v, *ctx, *y;
    cudaGetSymbolAddress((void**)&q,   g_q);
    cudaGetSymbolAddress((void**)&k,   g_k);
    cudaGetSymbolAddress((void**)&v,   g_v);
    cudaGetSymbolAddress((void**)&ctx, g_ctx);
    cudaGetSymbolAddress((void**)&y,   g_y);

    const dim3 blk(256);
    const dim3 g_proj(DD / 128, M_TOTAL / 128, 1);            // (8, 128)
    const dim3 g_ctx(DD / 128, DD / 128, BB);                 // (8, 8, 4)
    const dim3 g_y(DD / 128, NN_SEQ / 128, BB);               // (8, 32, 4)

    const float scale_ctx = 0.125f;          // 1/sqrt(D_HEAD=64)
    const float scale_y   = 1.0f / (float)DD;

    // 1) projections: q_lin, k_lin, v = x @ W
    sgemm_kernel<false, false><<<g_proj, blk>>>(x, Wq, q, nullptr,
        M_TOTAL, DD, DD, 1.0f, 0, 0, 0);
    sgemm_kernel<false, false><<<g_proj, blk>>>(x, Wk, k, nullptr,
        M_TOTAL, DD, DD, 1.0f, 0, 0, 0);
    sgemm_kernel<false, false><<<g_proj, blk>>>(x, Wv, v, nullptr,
        M_TOTAL, DD, DD, 1.0f, 0, 0, 0);

    // 2) softmaxes
    softmax_rows_kernel<<<M_TOTAL, 256>>>(q);                 // over features
    softmax_cols_kernel<<<dim3(DD / 32, BB), 256>>>(k);       // over sequence

    // 3) ctx = (k^T @ v) * scale, per batch:  [D,N]x[N,D] -> [D,D]
    sgemm_kernel<true, false><<<g_ctx, blk>>>(k, v, ctx, nullptr,
        DD, DD, NN_SEQ, scale_ctx,
        (size_t)NN_SEQ * DD, (size_t)NN_SEQ * DD, (size_t)DD * DD);

    // 4) y = (q @ ctx) / D_OUT, per batch:  [N,D]x[D,D] -> [N,D]
    sgemm_kernel<false, false><<<g_y, blk>>>(q, ctx, y, nullptr,
        NN_SEQ, DD, DD, scale_y,
        (size_t)NN_SEQ * DD, (size_t)DD * DD, (size_t)NN_SEQ * DD);

    // 5) out = y @ Wo + bo
    sgemm_kernel<false, true><<<g_proj, blk>>>(y, Wo, out, bo,
        M_TOTAL, DD, DD, 1.0f, 0, 0, 0);
}